// round 2
// baseline (speedup 1.0000x reference)
#include <cuda_runtime.h>
#include <math.h>

#define BB 4
#define NN 32768
#define CC 256
#define HH 8
#define DD 32
#define GG 32
#define HD 256          // H*D
#define SUB 32          // tokens per sub-tile
#define TOK_PER_BLK1 128
#define BLK_PER_BATCH (NN / TOK_PER_BLK1)       // 256
#define NBLK1 (BB * BLK_PER_BATCH)              // 1024

// ---------------- device scratch (allocation-free rule: globals) ------------
__device__ float g_slice_w[(size_t)BB * NN * HH * GG];        // [b][n][h][g]  134 MB
__device__ float g_part_tok[(size_t)NBLK1 * HH * GG * DD];    // [blk][h*G+g][d]
__device__ float g_part_norm[(size_t)NBLK1 * HH * GG];        // [blk][h*G+g]
__device__ float g_tokens[(size_t)BB * HH * GG * DD];         // [b][h][g][d]

// ---------------- fused 32x256 @ 256x256 GEMM (smem in, smem out) -----------
// Each thread owns one output column j=tid, 32 token accumulators.
__device__ __forceinline__ void gemm256(const float* __restrict__ s_in,
                                        const float* __restrict__ W,
                                        const float* __restrict__ bias,
                                        float* __restrict__ s_out, int tid)
{
    float acc[SUB];
    const float b0 = bias[tid];
#pragma unroll
    for (int t = 0; t < SUB; ++t) acc[t] = b0;
#pragma unroll 2
    for (int c = 0; c < CC; c += 4) {
        const float w0 = W[(c + 0) * HD + tid];
        const float w1 = W[(c + 1) * HD + tid];
        const float w2 = W[(c + 2) * HD + tid];
        const float w3 = W[(c + 3) * HD + tid];
#pragma unroll
        for (int t = 0; t < SUB; ++t) {
            const float4 f = *reinterpret_cast<const float4*>(&s_in[t * CC + c]);
            float a = acc[t];
            a = fmaf(f.x, w0, a);
            a = fmaf(f.y, w1, a);
            a = fmaf(f.z, w2, a);
            a = fmaf(f.w, w3, a);
            acc[t] = a;
        }
    }
#pragma unroll
    for (int t = 0; t < SUB; ++t) s_out[t * HD + tid] = acc[t];
}

// layer norm of 32x256 tile in smem, in place. warp w handles tokens 4w..4w+3
__device__ __forceinline__ void ln_tile(float* __restrict__ s_fxn,
                                        const float* __restrict__ ln_g,
                                        const float* __restrict__ ln_b,
                                        int warp, int lane)
{
    for (int t = warp * 4; t < warp * 4 + 4; ++t) {
        float s = 0.f, s2 = 0.f;
#pragma unroll
        for (int c = lane; c < CC; c += 32) {
            const float v = s_fxn[t * CC + c];
            s += v; s2 += v * v;
        }
#pragma unroll
        for (int o = 16; o; o >>= 1) {
            s  += __shfl_xor_sync(0xffffffffu, s,  o);
            s2 += __shfl_xor_sync(0xffffffffu, s2, o);
        }
        const float mu   = s * (1.f / CC);
        const float var  = s2 * (1.f / CC) - mu * mu;
        const float rstd = rsqrtf(var + 1e-5f);
#pragma unroll
        for (int c = lane; c < CC; c += 32) {
            const float v = s_fxn[t * CC + c];
            s_fxn[t * CC + c] = (v - mu) * rstd * ln_g[c] + ln_b[c];
        }
    }
}

// ---------------- K1: LN + x_mid/fx_mid GEMMs + slice_w + partial tokens ----
__global__ void __launch_bounds__(256, 2)
k1_dispatch(const float* __restrict__ fx,
            const float* __restrict__ ln_g, const float* __restrict__ ln_b,
            const float* __restrict__ Wx,  const float* __restrict__ bx,
            const float* __restrict__ Wfx, const float* __restrict__ bfx,
            const float* __restrict__ Ws,  const float* __restrict__ bs,
            const float* __restrict__ tempp)
{
    extern __shared__ float sm[];
    float* s_fxn = sm;                    // 32*256
    float* s_mid = sm + SUB * CC;         // 32*256 (x_mid, later fx_mid)
    float* s_w   = sm + 2 * SUB * CC;     // 32*256 (slice_w, [t][h*G+g])
    float* s_Ws  = sm + 3 * SUB * CC;     // 32*32
    float* s_bs  = s_Ws + DD * GG;        // 32

    const int tid  = threadIdx.x;
    const int warp = tid >> 5, lane = tid & 31;
    const int blk   = blockIdx.x;
    const int batch = blk / BLK_PER_BATCH;
    const int nbase = (blk % BLK_PER_BATCH) * TOK_PER_BLK1;

    for (int i = tid; i < DD * GG; i += 256) s_Ws[i] = Ws[i];
    if (tid < GG) s_bs[tid] = bs[tid];

    // accumulation mapping: warp = head, lane = g
    float accT[DD];
#pragma unroll
    for (int d = 0; d < DD; ++d) accT[d] = 0.f;
    float accN = 0.f;

    for (int sub = 0; sub < TOK_PER_BLK1 / SUB; ++sub) {
        const int n0 = nbase + sub * SUB;
        __syncthreads();   // protect smem reuse across iterations
        const float* fxp = fx + ((size_t)batch * NN + n0) * CC;
        for (int i = tid; i < SUB * CC; i += 256) s_fxn[i] = fxp[i];
        __syncthreads();

        ln_tile(s_fxn, ln_g, ln_b, warp, lane);
        __syncthreads();

        gemm256(s_fxn, Wx, bx, s_mid, tid);   // x_mid
        __syncthreads();

        // slice logits + softmax: warp = head, lane = g
        {
            float wsr[DD];
#pragma unroll
            for (int d = 0; d < DD; ++d) wsr[d] = s_Ws[d * GG + lane];
            const float bsg  = s_bs[lane];
            const float invt = 1.0f / tempp[warp];
            for (int t = 0; t < SUB; ++t) {
                float lg = bsg;
#pragma unroll
                for (int d = 0; d < DD; ++d)
                    lg = fmaf(s_mid[t * CC + warp * DD + d], wsr[d], lg);
                lg *= invt;
                float m = lg;
#pragma unroll
                for (int o = 16; o; o >>= 1) m = fmaxf(m, __shfl_xor_sync(0xffffffffu, m, o));
                const float e = __expf(lg - m);
                float ssum = e;
#pragma unroll
                for (int o = 16; o; o >>= 1) ssum += __shfl_xor_sync(0xffffffffu, ssum, o);
                const float wv = e / ssum;
                s_w[t * (HH * GG) + warp * GG + lane] = wv;
                g_slice_w[(((size_t)batch * NN + n0 + t) * HH + warp) * GG + lane] = wv;
            }
        }
        __syncthreads();

        gemm256(s_fxn, Wfx, bfx, s_mid, tid); // fx_mid
        __syncthreads();

        // accumulate slice_token partials: warp=h, lane=g
        for (int t = 0; t < SUB; ++t) {
            const float wv = s_w[t * (HH * GG) + warp * GG + lane];
            accN += wv;
#pragma unroll
            for (int d = 0; d < DD; ++d)
                accT[d] = fmaf(wv, s_mid[t * CC + warp * DD + d], accT[d]);
        }
    }

    float* pt = g_part_tok + ((size_t)blk * (HH * GG) + tid) * DD;
#pragma unroll
    for (int d = 0; d < DD; ++d) pt[d] = accT[d];
    g_part_norm[(size_t)blk * (HH * GG) + tid] = accN;
}

// ---------------- K2: reduce partials + attention + MLP  (tiny) -------------
__global__ void __launch_bounds__(1024)
k2_tokens(const float* __restrict__ Wq, const float* __restrict__ Wk,
          const float* __restrict__ Wv,
          const float* __restrict__ tln_g, const float* __restrict__ tln_b,
          const float* __restrict__ W1, const float* __restrict__ b1,
          const float* __restrict__ W2, const float* __restrict__ b2)
{
    const int b = blockIdx.x / HH;
    const int h = blockIdx.x % HH;
    const int tid = threadIdx.x;
    const int g = tid >> 5, d = tid & 31;   // warp = g, lane = d

    __shared__ float s_st[GG][DD + 1];
    __shared__ float s_q[GG][DD + 1], s_k[GG][DD + 1], s_v[GG][DD + 1];
    __shared__ float s_attn[GG][GG + 1];
    __shared__ float s_h1[GG][4 * DD];
    __shared__ float s_norm[GG];

    // deterministic partial reduction
    float tsum = 0.f;
#pragma unroll 4
    for (int pb = 0; pb < BLK_PER_BATCH; ++pb) {
        const size_t blk = (size_t)b * BLK_PER_BATCH + pb;
        tsum += g_part_tok[(blk * (HH * GG) + h * GG + g) * DD + d];
    }
    if (tid < GG) {
        float ns = 0.f;
#pragma unroll 4
        for (int pb = 0; pb < BLK_PER_BATCH; ++pb) {
            const size_t blk = (size_t)b * BLK_PER_BATCH + pb;
            ns += g_part_norm[blk * (HH * GG) + h * GG + tid];
        }
        s_norm[tid] = ns;
    }
    __syncthreads();

    const float st = tsum / (s_norm[g] + 1e-5f);
    s_st[g][d] = st;
    __syncthreads();

    // q, k, v
    float q = 0.f, kk = 0.f, vv = 0.f;
#pragma unroll
    for (int dd2 = 0; dd2 < DD; ++dd2) {
        const float sv = s_st[g][dd2];
        q  = fmaf(sv, Wq[dd2 * DD + d], q);
        kk = fmaf(sv, Wk[dd2 * DD + d], kk);
        vv = fmaf(sv, Wv[dd2 * DD + d], vv);
    }
    s_q[g][d] = q; s_k[g][d] = kk; s_v[g][d] = vv;
    __syncthreads();

    // attention logits + softmax; lane = key index
    {
        const int kidx = d;
        float lg = 0.f;
#pragma unroll
        for (int dd2 = 0; dd2 < DD; ++dd2)
            lg = fmaf(s_q[g][dd2], s_k[kidx][dd2], lg);
        lg *= 0.17677669529663687f;   // 32^-0.5
        float m = lg;
#pragma unroll
        for (int o = 16; o; o >>= 1) m = fmaxf(m, __shfl_xor_sync(0xffffffffu, m, o));
        const float e = __expf(lg - m);
        float ssum = e;
#pragma unroll
        for (int o = 16; o; o >>= 1) ssum += __shfl_xor_sync(0xffffffffu, ssum, o);
        s_attn[g][kidx] = e / ssum;
    }
    __syncthreads();

    float ot = st;   // residual slice_token
#pragma unroll
    for (int kidx = 0; kidx < GG; ++kidx)
        ot = fmaf(s_attn[g][kidx], s_v[kidx][d], ot);

    // token LN over D (within warp)
    float s1 = ot, s2o = ot * ot;
#pragma unroll
    for (int o = 16; o; o >>= 1) {
        s1  += __shfl_xor_sync(0xffffffffu, s1,  o);
        s2o += __shfl_xor_sync(0xffffffffu, s2o, o);
    }
    const float mu   = s1 * (1.f / DD);
    const float var  = s2o * (1.f / DD) - mu * mu;
    const float rstd = rsqrtf(var + 1e-5f);
    const float hn = (ot - mu) * rstd * tln_g[d] + tln_b[d];
    __syncthreads();           // s_st reuse
    s_st[g][d] = hn;
    __syncthreads();

    // MLP layer 1 + exact GELU
#pragma unroll
    for (int jj = 0; jj < 4; ++jj) {
        const int j = d + 32 * jj;
        float a = b1[j];
#pragma unroll
        for (int dd2 = 0; dd2 < DD; ++dd2)
            a = fmaf(s_st[g][dd2], W1[dd2 * (4 * DD) + j], a);
        a = 0.5f * a * (1.0f + erff(a * 0.70710678118654752f));
        s_h1[g][j] = a;
    }
    __syncthreads();

    // MLP layer 2 + residual out_tok
    float tk = b2[d];
#pragma unroll
    for (int j = 0; j < 4 * DD; ++j)
        tk = fmaf(s_h1[g][j], W2[j * DD + d], tk);
    tk += ot;
    g_tokens[(((size_t)b * HH + h) * GG + g) * DD + d] = tk;
}

// ---------------- K3: recompute LN, combine, Wo GEMM + residual -------------
__global__ void __launch_bounds__(256)
k3_combine(const float* __restrict__ fx,
           const float* __restrict__ ln_g, const float* __restrict__ ln_b,
           const float* __restrict__ Wo,  const float* __restrict__ bo,
           float* __restrict__ out)
{
    extern __shared__ float sm[];
    float* s_fxn = sm;                  // 32*256
    float* s_w   = sm + SUB * CC;       // 32*256
    float* s_mid = sm + 2 * SUB * CC;   // 32*256 (out_x)
    float* s_tok = sm + 3 * SUB * CC;   // 8*32*32

    const int tid  = threadIdx.x;
    const int warp = tid >> 5, lane = tid & 31;
    const int blk   = blockIdx.x;
    const int batch = blk / (NN / SUB);
    const int n0    = (blk % (NN / SUB)) * SUB;

    for (int i = tid; i < HH * GG * DD; i += 256)
        s_tok[i] = g_tokens[(size_t)batch * HH * GG * DD + i];
    const float* fxp = fx + ((size_t)batch * NN + n0) * CC;
    for (int i = tid; i < SUB * CC; i += 256) s_fxn[i] = fxp[i];
    const float* swp = g_slice_w + ((size_t)batch * NN + n0) * (HH * GG);
    for (int i = tid; i < SUB * HH * GG; i += 256) s_w[i] = swp[i];
    __syncthreads();

    ln_tile(s_fxn, ln_g, ln_b, warp, lane);   // fx_norm (residual + not needed by out_x)

    // out_x: warp = head, lane = d
    {
        float tokr[GG];
#pragma unroll
        for (int g2 = 0; g2 < GG; ++g2)
            tokr[g2] = s_tok[(warp * GG + g2) * DD + lane];
        for (int t = 0; t < SUB; ++t) {
            float a = 0.f;
#pragma unroll
            for (int g2 = 0; g2 < GG; ++g2)
                a = fmaf(tokr[g2], s_w[t * (HH * GG) + warp * GG + g2], a);
            s_mid[t * CC + warp * DD + lane] = a;
        }
    }
    __syncthreads();

    // Wo GEMM + bias + fx_norm residual, streamed to gmem
    float acc[SUB];
    const float b0 = bo[tid];
#pragma unroll
    for (int t = 0; t < SUB; ++t) acc[t] = b0;
#pragma unroll 2
    for (int c = 0; c < CC; c += 4) {
        const float w0 = Wo[(c + 0) * CC + tid];
        const float w1 = Wo[(c + 1) * CC + tid];
        const float w2 = Wo[(c + 2) * CC + tid];
        const float w3 = Wo[(c + 3) * CC + tid];
#pragma unroll
        for (int t = 0; t < SUB; ++t) {
            const float4 f = *reinterpret_cast<const float4*>(&s_mid[t * CC + c]);
            float a = acc[t];
            a = fmaf(f.x, w0, a);
            a = fmaf(f.y, w1, a);
            a = fmaf(f.z, w2, a);
            a = fmaf(f.w, w3, a);
            acc[t] = a;
        }
    }
    float* op = out + ((size_t)batch * NN + n0) * CC;
#pragma unroll
    for (int t = 0; t < SUB; ++t)
        op[t * CC + tid] = acc[t] + s_fxn[t * CC + tid];
}

// ---------------- launch -----------------------------------------------------
extern "C" void kernel_launch(void* const* d_in, const int* in_sizes, int n_in,
                              void* d_out, int out_size)
{
    const float* fx    = (const float*)d_in[0];
    const float* ln_g  = (const float*)d_in[1];
    const float* ln_b  = (const float*)d_in[2];
    const float* Wx    = (const float*)d_in[3];
    const float* bx    = (const float*)d_in[4];
    const float* Wfx   = (const float*)d_in[5];
    const float* bfx   = (const float*)d_in[6];
    const float* Ws    = (const float*)d_in[7];
    const float* bs    = (const float*)d_in[8];
    const float* tempp = (const float*)d_in[9];
    const float* Wq    = (const float*)d_in[10];
    const float* Wk    = (const float*)d_in[11];
    const float* Wv    = (const float*)d_in[12];
    const float* tln_g = (const float*)d_in[13];
    const float* tln_b = (const float*)d_in[14];
    const float* W1    = (const float*)d_in[15];
    const float* b1    = (const float*)d_in[16];
    const float* W2    = (const float*)d_in[17];
    const float* b2    = (const float*)d_in[18];
    const float* Wo    = (const float*)d_in[19];
    const float* bo    = (const float*)d_in[20];
    float* out = (float*)d_out;

    const int smem1 = (3 * SUB * CC + DD * GG + GG) * (int)sizeof(float);     // ~100 KB
    const int smem3 = (3 * SUB * CC + HH * GG * DD) * (int)sizeof(float);     // 128 KB
    cudaFuncSetAttribute(k1_dispatch, cudaFuncAttributeMaxDynamicSharedMemorySize, smem1);
    cudaFuncSetAttribute(k3_combine,  cudaFuncAttributeMaxDynamicSharedMemorySize, smem3);

    k1_dispatch<<<NBLK1, 256, smem1>>>(fx, ln_g, ln_b, Wx, bx, Wfx, bfx, Ws, bs, tempp);
    k2_tokens<<<BB * HH, 1024>>>(Wq, Wk, Wv, tln_g, tln_b, W1, b1, W2, b2);
    k3_combine<<<BB * (NN / SUB), 256, smem3>>>(fx, ln_g, ln_b, Wo, bo, out);
}

// round 3
// speedup vs baseline: 1.2141x; 1.2141x over previous
#include <cuda_runtime.h>
#include <math.h>

#define BB 4
#define NN 32768
#define CC 256
#define HH 8
#define DD 32
#define GG 32
#define TOK 64                      // tokens per block tile
#define BLKS_PER_BATCH (NN / TOK)   // 512
#define NBLK (BB * BLKS_PER_BATCH)  // 2048

// ---------------- device scratch (allocation-free rule) ---------------------
__device__ float g_slice_w[(size_t)BB * NN * HH * GG];        // [b][n][h][g]
__device__ float g_part_tok[(size_t)NBLK * HH * GG * DD];     // [blk][h*G+g][d]
__device__ float g_part_norm[(size_t)NBLK * HH * GG];         // [blk][h*G+g]
__device__ float g_tokens[(size_t)BB * HH * GG * DD];         // [b][h][g][d]

typedef unsigned long long u64;

__device__ __forceinline__ void fma2(u64& d, u64 a, u64 b) {
    asm("fma.rn.f32x2 %0, %1, %2, %0;" : "+l"(d) : "l"(a), "l"(b));
}
__device__ __forceinline__ float2 unpack2(u64 v) {
    float2 f;
    asm("mov.b64 {%0, %1}, %2;" : "=f"(f.x), "=f"(f.y) : "l"(v));
    return f;
}

// ---------------- FFMA2 GEMM: 64x256 tile @ 256x256 W -----------------------
// 256 threads: warp tg owns tokens tg*8..tg*8+7; lane owns cols {lane+32j}.
// W staged in smem as k-pair-interleaved float2 panels, double buffered.
// acc[t][j] is a f32x2 holding even-k / odd-k partial sums.
template<int KP>
__device__ __forceinline__ void gemm2(const float* __restrict__ s_in,
                                      const float* __restrict__ Wg,
                                      const float* __restrict__ bias,
                                      float* __restrict__ s_out,
                                      float* __restrict__ s_pan)
{
    const int tid  = threadIdx.x;
    const int tg   = tid >> 5;
    const int lane = tid & 31;
    constexpr int NPAN  = CC / KP;
    constexpr int PAIRS = KP / 2;       // float2 pairs staged per thread
    constexpr int PANF  = KP * CC;      // floats per panel buffer

    u64 acc[8][8];
#pragma unroll
    for (int t = 0; t < 8; ++t)
#pragma unroll
        for (int j = 0; j < 8; ++j) acc[t][j] = 0ull;

    // stage panel 0
#pragma unroll
    for (int i = 0; i < PAIRS; ++i) {
        const int p = tid + i * 256;
        const int kkp = p >> 8, c = p & 255;
        float2 w = make_float2(Wg[(2 * kkp) * CC + c], Wg[(2 * kkp + 1) * CC + c]);
        *reinterpret_cast<float2*>(&s_pan[2 * p]) = w;
    }
    __syncthreads();

#pragma unroll 1
    for (int pan = 0; pan < NPAN; ++pan) {
        float2 nw[PAIRS];
        if (pan + 1 < NPAN) {
            const float* Wn = Wg + (pan + 1) * KP * CC;
#pragma unroll
            for (int i = 0; i < PAIRS; ++i) {
                const int p = tid + i * 256;
                const int kkp = p >> 8, c = p & 255;
                nw[i] = make_float2(Wn[(2 * kkp) * CC + c], Wn[(2 * kkp + 1) * CC + c]);
            }
        }
        const float* pb = s_pan + (pan & 1) * PANF;
        const int k0 = pan * KP;
#pragma unroll
        for (int kkp = 0; kkp < KP / 2; ++kkp) {
            u64 b[8];
#pragma unroll
            for (int j = 0; j < 8; ++j)
                b[j] = *reinterpret_cast<const u64*>(&pb[kkp * 512 + (lane + 32 * j) * 2]);
#pragma unroll
            for (int t = 0; t < 8; ++t) {
                const u64 a = *reinterpret_cast<const u64*>(
                    &s_in[(tg * 8 + t) * CC + k0 + kkp * 2]);
#pragma unroll
                for (int j = 0; j < 8; ++j) fma2(acc[t][j], a, b[j]);
            }
        }
        if (pan + 1 < NPAN) {
            float* pbn = s_pan + ((pan + 1) & 1) * PANF;
#pragma unroll
            for (int i = 0; i < PAIRS; ++i)
                *reinterpret_cast<float2*>(&pbn[2 * (tid + i * 256)]) = nw[i];
        }
        __syncthreads();
    }

    float br[8];
#pragma unroll
    for (int j = 0; j < 8; ++j) br[j] = bias[lane + 32 * j];
#pragma unroll
    for (int t = 0; t < 8; ++t)
#pragma unroll
        for (int j = 0; j < 8; ++j) {
            const float2 f = unpack2(acc[t][j]);
            s_out[(tg * 8 + t) * CC + lane + 32 * j] = f.x + f.y + br[j];
        }
}

// layer norm in-place: warp tg handles rows tg*8..tg*8+7 of a [rows x 256] tile
__device__ __forceinline__ void ln_rows(float* __restrict__ s_t,
                                        const float* __restrict__ ln_g,
                                        const float* __restrict__ ln_b,
                                        int tg, int lane)
{
    for (int t = tg * 8; t < tg * 8 + 8; ++t) {
        float s = 0.f, s2 = 0.f;
#pragma unroll
        for (int c = lane; c < CC; c += 32) {
            const float v = s_t[t * CC + c];
            s += v; s2 += v * v;
        }
#pragma unroll
        for (int o = 16; o; o >>= 1) {
            s  += __shfl_xor_sync(0xffffffffu, s,  o);
            s2 += __shfl_xor_sync(0xffffffffu, s2, o);
        }
        const float mu   = s * (1.f / CC);
        const float var  = s2 * (1.f / CC) - mu * mu;
        const float rstd = rsqrtf(var + 1e-5f);
#pragma unroll
        for (int c = lane; c < CC; c += 32) {
            const float v = s_t[t * CC + c];
            s_t[t * CC + c] = (v - mu) * rstd * ln_g[c] + ln_b[c];
        }
    }
}

// ---------------- K1: LN + x_mid/fx_mid GEMMs + slice_w + partial tokens ----
__global__ void __launch_bounds__(256, 1)
k1_dispatch(const float* __restrict__ fx,
            const float* __restrict__ ln_g, const float* __restrict__ ln_b,
            const float* __restrict__ Wx,  const float* __restrict__ bx,
            const float* __restrict__ Wfx, const float* __restrict__ bfx,
            const float* __restrict__ Ws,  const float* __restrict__ bs,
            const float* __restrict__ tempp)
{
    extern __shared__ float sm[];
    float* s_A   = sm;                   // 64x256  fx -> fx_norm -> fx_mid
    float* s_B   = sm + TOK * CC;        // 64x256  x_mid -> slice_w
    float* s_pan = sm + 2 * TOK * CC;    // 2*16*256 = 8192
    float* s_Ws  = s_pan + 8192;         // 32*32
    float* s_bs  = s_Ws + DD * GG;       // 32

    const int tid  = threadIdx.x;
    const int tg   = tid >> 5;
    const int lane = tid & 31;
    const int batch = blockIdx.x / BLKS_PER_BATCH;
    const int n0    = (blockIdx.x % BLKS_PER_BATCH) * TOK;

    for (int i = tid; i < DD * GG; i += 256) s_Ws[i] = Ws[i];
    if (tid < GG) s_bs[tid] = bs[tid];

    const float* fxp = fx + ((size_t)batch * NN + n0) * CC;
    for (int i = tid * 4; i < TOK * CC; i += 1024)
        *reinterpret_cast<float4*>(&s_A[i]) = *reinterpret_cast<const float4*>(&fxp[i]);
    __syncthreads();

    ln_rows(s_A, ln_g, ln_b, tg, lane);
    __syncthreads();

    gemm2<16>(s_A, Wx, bx, s_B, s_pan);   // x_mid
    __syncthreads();

    // slice logits + softmax, in-place on s_B rows tg*8..+7; lane = g
    {
        float invt[HH];
#pragma unroll
        for (int h = 0; h < HH; ++h) invt[h] = 1.0f / tempp[h];
        const int g = lane;
        const float bsg = s_bs[g];
        float wsr[DD];
#pragma unroll
        for (int d = 0; d < DD; ++d) wsr[d] = s_Ws[d * GG + g];
        for (int i = 0; i < 64; ++i) {
            const int t = tg * 8 + (i >> 3);
            const int h = i & 7;
            float lg = bsg;
#pragma unroll
            for (int d = 0; d < DD; ++d)
                lg = fmaf(s_B[t * CC + h * DD + d], wsr[d], lg);
            lg *= invt[h];
            float m = lg;
#pragma unroll
            for (int o = 16; o; o >>= 1) m = fmaxf(m, __shfl_xor_sync(0xffffffffu, m, o));
            const float e = __expf(lg - m);
            float ssum = e;
#pragma unroll
            for (int o = 16; o; o >>= 1) ssum += __shfl_xor_sync(0xffffffffu, ssum, o);
            const float wv = e / ssum;
            __syncwarp();
            s_B[t * CC + h * GG + g] = wv;
            g_slice_w[(((size_t)batch * NN + n0 + t) * HH + h) * GG + g] = wv;
        }
    }
    __syncthreads();

    gemm2<16>(s_A, Wfx, bfx, s_A, s_pan);  // fx_mid, in-place (warp-exclusive rows)
    __syncthreads();

    // accumulate slice_token partials: warp tg = head, lane = g
    {
        const int h = tg, g = lane;
        float accT[DD];
#pragma unroll
        for (int d = 0; d < DD; ++d) accT[d] = 0.f;
        float accN = 0.f;
        for (int t = 0; t < TOK; ++t) {
            const float wv = s_B[t * CC + h * GG + g];
            accN += wv;
#pragma unroll
            for (int d = 0; d < DD; ++d)
                accT[d] = fmaf(wv, s_A[t * CC + h * DD + d], accT[d]);
        }
        float* pt = g_part_tok + ((size_t)blockIdx.x * (HH * GG) + tid) * DD;
#pragma unroll
        for (int d = 0; d < DD; ++d) pt[d] = accT[d];
        g_part_norm[(size_t)blockIdx.x * (HH * GG) + tid] = accN;
    }
}

// ---------------- K2: reduce partials + attention + MLP  (tiny) -------------
__global__ void __launch_bounds__(1024)
k2_tokens(const float* __restrict__ Wq, const float* __restrict__ Wk,
          const float* __restrict__ Wv,
          const float* __restrict__ tln_g, const float* __restrict__ tln_b,
          const float* __restrict__ W1, const float* __restrict__ b1,
          const float* __restrict__ W2, const float* __restrict__ b2)
{
    const int b = blockIdx.x / HH;
    const int h = blockIdx.x % HH;
    const int tid = threadIdx.x;
    const int g = tid >> 5, d = tid & 31;

    __shared__ float s_st[GG][DD + 1];
    __shared__ float s_q[GG][DD + 1], s_k[GG][DD + 1], s_v[GG][DD + 1];
    __shared__ float s_attn[GG][GG + 1];
    __shared__ float s_h1[GG][4 * DD];
    __shared__ float s_norm[GG];

    float tsum = 0.f;
#pragma unroll 4
    for (int pb = 0; pb < BLKS_PER_BATCH; ++pb) {
        const size_t blk = (size_t)b * BLKS_PER_BATCH + pb;
        tsum += g_part_tok[(blk * (HH * GG) + h * GG + g) * DD + d];
    }
    if (tid < GG) {
        float ns = 0.f;
#pragma unroll 4
        for (int pb = 0; pb < BLKS_PER_BATCH; ++pb) {
            const size_t blk = (size_t)b * BLKS_PER_BATCH + pb;
            ns += g_part_norm[blk * (HH * GG) + h * GG + tid];
        }
        s_norm[tid] = ns;
    }
    __syncthreads();

    const float st = tsum / (s_norm[g] + 1e-5f);
    s_st[g][d] = st;
    __syncthreads();

    float q = 0.f, kk = 0.f, vv = 0.f;
#pragma unroll
    for (int dd2 = 0; dd2 < DD; ++dd2) {
        const float sv = s_st[g][dd2];
        q  = fmaf(sv, Wq[dd2 * DD + d], q);
        kk = fmaf(sv, Wk[dd2 * DD + d], kk);
        vv = fmaf(sv, Wv[dd2 * DD + d], vv);
    }
    s_q[g][d] = q; s_k[g][d] = kk; s_v[g][d] = vv;
    __syncthreads();

    {
        const int kidx = d;
        float lg = 0.f;
#pragma unroll
        for (int dd2 = 0; dd2 < DD; ++dd2)
            lg = fmaf(s_q[g][dd2], s_k[kidx][dd2], lg);
        lg *= 0.17677669529663687f;
        float m = lg;
#pragma unroll
        for (int o = 16; o; o >>= 1) m = fmaxf(m, __shfl_xor_sync(0xffffffffu, m, o));
        const float e = __expf(lg - m);
        float ssum = e;
#pragma unroll
        for (int o = 16; o; o >>= 1) ssum += __shfl_xor_sync(0xffffffffu, ssum, o);
        s_attn[g][kidx] = e / ssum;
    }
    __syncthreads();

    float ot = st;
#pragma unroll
    for (int kidx = 0; kidx < GG; ++kidx)
        ot = fmaf(s_attn[g][kidx], s_v[kidx][d], ot);

    float s1 = ot, s2o = ot * ot;
#pragma unroll
    for (int o = 16; o; o >>= 1) {
        s1  += __shfl_xor_sync(0xffffffffu, s1,  o);
        s2o += __shfl_xor_sync(0xffffffffu, s2o, o);
    }
    const float mu   = s1 * (1.f / DD);
    const float var  = s2o * (1.f / DD) - mu * mu;
    const float rstd = rsqrtf(var + 1e-5f);
    const float hn = (ot - mu) * rstd * tln_g[d] + tln_b[d];
    __syncthreads();
    s_st[g][d] = hn;
    __syncthreads();

#pragma unroll
    for (int jj = 0; jj < 4; ++jj) {
        const int j = d + 32 * jj;
        float a = b1[j];
#pragma unroll
        for (int dd2 = 0; dd2 < DD; ++dd2)
            a = fmaf(s_st[g][dd2], W1[dd2 * (4 * DD) + j], a);
        a = 0.5f * a * (1.0f + erff(a * 0.70710678118654752f));
        s_h1[g][j] = a;
    }
    __syncthreads();

    float tk = b2[d];
#pragma unroll
    for (int j = 0; j < 4 * DD; ++j)
        tk = fmaf(s_h1[g][j], W2[j * DD + d], tk);
    tk += ot;
    g_tokens[(((size_t)b * HH + h) * GG + g) * DD + d] = tk;
}

// ---------------- K3: LN, combine, Wo GEMM + residual -----------------------
__global__ void __launch_bounds__(256, 1)
k3_combine(const float* __restrict__ fx,
           const float* __restrict__ ln_g, const float* __restrict__ ln_b,
           const float* __restrict__ Wo,  const float* __restrict__ bo,
           float* __restrict__ out)
{
    extern __shared__ float sm[];
    float* s_A   = sm;                   // fx -> fx_norm
    float* s_B   = sm + TOK * CC;        // slice_w
    float* s_C   = sm + 2 * TOK * CC;    // out_x -> Wo result
    float* s_pan = sm + 3 * TOK * CC;    // 2*8*256 = 4096

    const int tid  = threadIdx.x;
    const int tg   = tid >> 5;
    const int lane = tid & 31;
    const int batch = blockIdx.x / BLKS_PER_BATCH;
    const int n0    = (blockIdx.x % BLKS_PER_BATCH) * TOK;

    const float* fxp = fx + ((size_t)batch * NN + n0) * CC;
    for (int i = tid * 4; i < TOK * CC; i += 1024)
        *reinterpret_cast<float4*>(&s_A[i]) = *reinterpret_cast<const float4*>(&fxp[i]);
    const float* swp = g_slice_w + ((size_t)batch * NN + n0) * (HH * GG);
    for (int i = tid * 4; i < TOK * (HH * GG); i += 1024)
        *reinterpret_cast<float4*>(&s_B[i]) = *reinterpret_cast<const float4*>(&swp[i]);

    // tokens for head h=tg, component d=lane, all g: registers
    float tokr[GG];
#pragma unroll
    for (int g = 0; g < GG; ++g)
        tokr[g] = g_tokens[(((size_t)batch * HH + tg) * GG + g) * DD + lane];
    __syncthreads();

    ln_rows(s_A, ln_g, ln_b, tg, lane);

    // out_x: warp tg = head, lane = d
    for (int t = 0; t < TOK; ++t) {
        float a = 0.f;
#pragma unroll
        for (int g = 0; g < GG; ++g)
            a = fmaf(tokr[g], s_B[t * CC + tg * GG + g], a);
        s_C[t * CC + tg * DD + lane] = a;
    }
    __syncthreads();

    gemm2<8>(s_C, Wo, bo, s_C, s_pan);   // in-place (warp-exclusive rows)
    __syncthreads();

    float* op = out + ((size_t)batch * NN + n0) * CC;
    for (int i = tid * 4; i < TOK * CC; i += 1024) {
        float4 c4 = *reinterpret_cast<float4*>(&s_C[i]);
        const float4 a4 = *reinterpret_cast<const float4*>(&s_A[i]);
        c4.x += a4.x; c4.y += a4.y; c4.z += a4.z; c4.w += a4.w;
        *reinterpret_cast<float4*>(&op[i]) = c4;
    }
}

// ---------------- launch -----------------------------------------------------
extern "C" void kernel_launch(void* const* d_in, const int* in_sizes, int n_in,
                              void* d_out, int out_size)
{
    const float* fx    = (const float*)d_in[0];
    const float* ln_g  = (const float*)d_in[1];
    const float* ln_b  = (const float*)d_in[2];
    const float* Wx    = (const float*)d_in[3];
    const float* bx    = (const float*)d_in[4];
    const float* Wfx   = (const float*)d_in[5];
    const float* bfx   = (const float*)d_in[6];
    const float* Ws    = (const float*)d_in[7];
    const float* bs    = (const float*)d_in[8];
    const float* tempp = (const float*)d_in[9];
    const float* Wq    = (const float*)d_in[10];
    const float* Wk    = (const float*)d_in[11];
    const float* Wv    = (const float*)d_in[12];
    const float* tln_g = (const float*)d_in[13];
    const float* tln_b = (const float*)d_in[14];
    const float* W1    = (const float*)d_in[15];
    const float* b1    = (const float*)d_in[16];
    const float* W2    = (const float*)d_in[17];
    const float* b2    = (const float*)d_in[18];
    const float* Wo    = (const float*)d_in[19];
    const float* bo    = (const float*)d_in[20];
    float* out = (float*)d_out;

    const int smem1 = (2 * TOK * CC + 8192 + DD * GG + GG) * (int)sizeof(float); // ~168KB
    const int smem3 = (3 * TOK * CC + 4096) * (int)sizeof(float);                // ~208KB
    static int s_init = 0;
    if (!s_init) {
        cudaFuncSetAttribute(k1_dispatch, cudaFuncAttributeMaxDynamicSharedMemorySize, smem1);
        cudaFuncSetAttribute(k3_combine,  cudaFuncAttributeMaxDynamicSharedMemorySize, smem3);
        s_init = 1;
    }

    k1_dispatch<<<NBLK, 256, smem1>>>(fx, ln_g, ln_b, Wx, bx, Wfx, bfx, Ws, bs, tempp);
    k2_tokens<<<BB * HH, 1024>>>(Wq, Wk, Wv, tln_g, tln_b, W1, b1, W2, b2);
    k3_combine<<<NBLK, 256, smem3>>>(fx, ln_g, ln_b, Wo, bo, out);
}

// round 4
// speedup vs baseline: 1.4341x; 1.1812x over previous
#include <cuda_runtime.h>
#include <math.h>

#define BB 4
#define NN 32768
#define CC 256
#define HH 8
#define DD 32
#define GG 32
#define TOK 32                      // tokens per block tile
#define TPW (TOK / 8)               // tokens per warp = 4
#define BLKS_PER_BATCH (NN / TOK)   // 1024
#define NBLK (BB * BLKS_PER_BATCH)  // 4096

// ---------------- device scratch (allocation-free rule) ---------------------
__device__ float g_slice_w[(size_t)BB * NN * HH * GG];        // [b][n][h][g]
__device__ float g_part_tok[(size_t)NBLK * HH * GG * DD];     // [blk][h*G+g][d]
__device__ float g_part_norm[(size_t)NBLK * HH * GG];         // [blk][h*G+g]
__device__ float g_tokens[(size_t)BB * HH * GG * DD];         // [b][h][g][d]

typedef unsigned long long u64;

__device__ __forceinline__ void fma2(u64& d, u64 a, u64 b) {
    asm("fma.rn.f32x2 %0, %1, %2, %0;" : "+l"(d) : "l"(a), "l"(b));
}
__device__ __forceinline__ float2 unpack2(u64 v) {
    float2 f;
    asm("mov.b64 {%0, %1}, %2;" : "=f"(f.x), "=f"(f.y) : "l"(v));
    return f;
}

// ---------------- FFMA2 GEMM: TOKx256 tile @ 256x256 W ----------------------
// 256 threads: warp tg owns tokens tg*TPW..+TPW-1; lane owns cols {lane+32j}.
// W staged in smem as k-pair-interleaved float2 panels, double buffered.
// acc[t][j] is f32x2 (even-k / odd-k partials). Reads of s_in are
// warp-row-exclusive, so s_out may alias s_in.
template<int KP>
__device__ __forceinline__ void gemm2(const float* __restrict__ s_in,
                                      const float* __restrict__ Wg,
                                      const float* __restrict__ bias,
                                      float* __restrict__ s_out,
                                      float* __restrict__ s_pan)
{
    const int tid  = threadIdx.x;
    const int tg   = tid >> 5;
    const int lane = tid & 31;
    constexpr int NPAN  = CC / KP;
    constexpr int PAIRS = (KP * 128) / 256;   // float2 per thread per panel
    constexpr int PANF  = KP * CC;

    u64 acc[TPW][8];
#pragma unroll
    for (int t = 0; t < TPW; ++t)
#pragma unroll
        for (int j = 0; j < 8; ++j) acc[t][j] = 0ull;

#pragma unroll
    for (int i = 0; i < PAIRS; ++i) {
        const int p = tid + i * 256;
        const int kkp = p >> 8, c = p & 255;
        float2 w = make_float2(Wg[(2 * kkp) * CC + c], Wg[(2 * kkp + 1) * CC + c]);
        *reinterpret_cast<float2*>(&s_pan[2 * p]) = w;
    }
    __syncthreads();

#pragma unroll 1
    for (int pan = 0; pan < NPAN; ++pan) {
        float2 nw[PAIRS];
        if (pan + 1 < NPAN) {
            const float* Wn = Wg + (pan + 1) * KP * CC;
#pragma unroll
            for (int i = 0; i < PAIRS; ++i) {
                const int p = tid + i * 256;
                const int kkp = p >> 8, c = p & 255;
                nw[i] = make_float2(Wn[(2 * kkp) * CC + c], Wn[(2 * kkp + 1) * CC + c]);
            }
        }
        const float* pb = s_pan + (pan & 1) * PANF;
        const int k0 = pan * KP;
#pragma unroll
        for (int kkp = 0; kkp < KP / 2; ++kkp) {
            u64 b[8];
#pragma unroll
            for (int j = 0; j < 8; ++j)
                b[j] = *reinterpret_cast<const u64*>(&pb[kkp * 512 + (lane + 32 * j) * 2]);
#pragma unroll
            for (int t = 0; t < TPW; ++t) {
                const u64 a = *reinterpret_cast<const u64*>(
                    &s_in[(tg * TPW + t) * CC + k0 + kkp * 2]);
#pragma unroll
                for (int j = 0; j < 8; ++j) fma2(acc[t][j], a, b[j]);
            }
        }
        if (pan + 1 < NPAN) {
            float* pbn = s_pan + ((pan + 1) & 1) * PANF;
#pragma unroll
            for (int i = 0; i < PAIRS; ++i)
                *reinterpret_cast<float2*>(&pbn[2 * (tid + i * 256)]) = nw[i];
        }
        __syncthreads();
    }

    float br[8];
#pragma unroll
    for (int j = 0; j < 8; ++j) br[j] = bias[lane + 32 * j];
#pragma unroll
    for (int t = 0; t < TPW; ++t)
#pragma unroll
        for (int j = 0; j < 8; ++j) {
            const float2 f = unpack2(acc[t][j]);
            s_out[(tg * TPW + t) * CC + lane + 32 * j] = f.x + f.y + br[j];
        }
}

// layer norm in-place: warp tg handles rows tg*TPW..+TPW-1 of [TOK x 256]
__device__ __forceinline__ void ln_rows(float* __restrict__ s_t,
                                        const float* __restrict__ ln_g,
                                        const float* __restrict__ ln_b,
                                        int tg, int lane)
{
#pragma unroll
    for (int t = tg * TPW; t < tg * TPW + TPW; ++t) {
        float s = 0.f, s2 = 0.f;
#pragma unroll
        for (int c = lane; c < CC; c += 32) {
            const float v = s_t[t * CC + c];
            s += v; s2 += v * v;
        }
#pragma unroll
        for (int o = 16; o; o >>= 1) {
            s  += __shfl_xor_sync(0xffffffffu, s,  o);
            s2 += __shfl_xor_sync(0xffffffffu, s2, o);
        }
        const float mu   = s * (1.f / CC);
        const float var  = s2 * (1.f / CC) - mu * mu;
        const float rstd = rsqrtf(var + 1e-5f);
#pragma unroll
        for (int c = lane; c < CC; c += 32) {
            const float v = s_t[t * CC + c];
            s_t[t * CC + c] = (v - mu) * rstd * ln_g[c] + ln_b[c];
        }
    }
}

// ---------------- K1: LN + x_mid/fx_mid GEMMs + slice_w + partial tokens ----
__global__ void __launch_bounds__(256, 2)
k1_dispatch(const float* __restrict__ fx,
            const float* __restrict__ ln_g, const float* __restrict__ ln_b,
            const float* __restrict__ Wx,  const float* __restrict__ bx,
            const float* __restrict__ Wfx, const float* __restrict__ bfx,
            const float* __restrict__ Ws,  const float* __restrict__ bs,
            const float* __restrict__ tempp)
{
    extern __shared__ float sm[];
    float* s_A   = sm;                   // TOKx256  fx -> fx_norm -> fx_mid
    float* s_B   = sm + TOK * CC;        // TOKx256  x_mid -> slice_w
    float* s_pan = sm + 2 * TOK * CC;    // 2*16*256 = 8192
    float* s_Ws  = s_pan + 8192;         // 32*32
    float* s_bs  = s_Ws + DD * GG;       // 32

    const int tid  = threadIdx.x;
    const int tg   = tid >> 5;
    const int lane = tid & 31;
    const int batch = blockIdx.x / BLKS_PER_BATCH;
    const int n0    = (blockIdx.x % BLKS_PER_BATCH) * TOK;

    for (int i = tid; i < DD * GG; i += 256) s_Ws[i] = Ws[i];
    if (tid < GG) s_bs[tid] = bs[tid];

    const float* fxp = fx + ((size_t)batch * NN + n0) * CC;
    for (int i = tid * 4; i < TOK * CC; i += 1024)
        *reinterpret_cast<float4*>(&s_A[i]) = *reinterpret_cast<const float4*>(&fxp[i]);
    __syncthreads();

    ln_rows(s_A, ln_g, ln_b, tg, lane);
    __syncthreads();

    gemm2<16>(s_A, Wx, bx, s_B, s_pan);   // x_mid
    __syncthreads();

    // slice logits + softmax, in-place on warp-own rows of s_B; lane = g
    {
        float invt[HH];
#pragma unroll
        for (int h = 0; h < HH; ++h) invt[h] = 1.0f / tempp[h];
        const int g = lane;
        const float bsg = s_bs[g];
        float wsr[DD];
#pragma unroll
        for (int d = 0; d < DD; ++d) wsr[d] = s_Ws[d * GG + g];
        for (int i = 0; i < TPW * HH; ++i) {
            const int t = tg * TPW + (i >> 3);
            const int h = i & 7;
            float lg = bsg;
#pragma unroll
            for (int d = 0; d < DD; ++d)
                lg = fmaf(s_B[t * CC + h * DD + d], wsr[d], lg);
            lg *= invt[h];
            float m = lg;
#pragma unroll
            for (int o = 16; o; o >>= 1) m = fmaxf(m, __shfl_xor_sync(0xffffffffu, m, o));
            const float e = __expf(lg - m);
            float ssum = e;
#pragma unroll
            for (int o = 16; o; o >>= 1) ssum += __shfl_xor_sync(0xffffffffu, ssum, o);
            const float wv = e / ssum;
            __syncwarp();
            s_B[t * CC + h * GG + g] = wv;
            g_slice_w[(((size_t)batch * NN + n0 + t) * HH + h) * GG + g] = wv;
        }
    }
    __syncthreads();

    gemm2<16>(s_A, Wfx, bfx, s_A, s_pan);  // fx_mid, in-place
    __syncthreads();

    // accumulate slice_token partials: warp tg = head, lane = g
    {
        const int h = tg, g = lane;
        float accT[DD];
#pragma unroll
        for (int d = 0; d < DD; ++d) accT[d] = 0.f;
        float accN = 0.f;
        for (int t = 0; t < TOK; ++t) {
            const float wv = s_B[t * CC + h * GG + g];
            accN += wv;
#pragma unroll
            for (int d = 0; d < DD; ++d)
                accT[d] = fmaf(wv, s_A[t * CC + h * DD + d], accT[d]);
        }
        float* pt = g_part_tok + ((size_t)blockIdx.x * (HH * GG) + tid) * DD;
#pragma unroll
        for (int d = 0; d < DD; d += 4)
            *reinterpret_cast<float4*>(&pt[d]) =
                make_float4(accT[d], accT[d + 1], accT[d + 2], accT[d + 3]);
        g_part_norm[(size_t)blockIdx.x * (HH * GG) + tid] = accN;
    }
}

// ---------------- K2: reduce partials + attention + MLP  (tiny) -------------
__global__ void __launch_bounds__(1024)
k2_tokens(const float* __restrict__ Wq, const float* __restrict__ Wk,
          const float* __restrict__ Wv,
          const float* __restrict__ tln_g, const float* __restrict__ tln_b,
          const float* __restrict__ W1, const float* __restrict__ b1,
          const float* __restrict__ W2, const float* __restrict__ b2)
{
    const int b = blockIdx.x / HH;
    const int h = blockIdx.x % HH;
    const int tid = threadIdx.x;
    const int g = tid >> 5, d = tid & 31;

    __shared__ float s_st[GG][DD + 1];
    __shared__ float s_q[GG][DD + 1], s_k[GG][DD + 1], s_v[GG][DD + 1];
    __shared__ float s_attn[GG][GG + 1];
    __shared__ float s_h1[GG][4 * DD];
    __shared__ float s_norm[GG];

    float tsum = 0.f;
#pragma unroll 4
    for (int pb = 0; pb < BLKS_PER_BATCH; ++pb) {
        const size_t blk = (size_t)b * BLKS_PER_BATCH + pb;
        tsum += g_part_tok[(blk * (HH * GG) + h * GG + g) * DD + d];
    }
    if (tid < GG) {
        float ns = 0.f;
#pragma unroll 4
        for (int pb = 0; pb < BLKS_PER_BATCH; ++pb) {
            const size_t blk = (size_t)b * BLKS_PER_BATCH + pb;
            ns += g_part_norm[blk * (HH * GG) + h * GG + tid];
        }
        s_norm[tid] = ns;
    }
    __syncthreads();

    const float st = tsum / (s_norm[g] + 1e-5f);
    s_st[g][d] = st;
    __syncthreads();

    float q = 0.f, kk = 0.f, vv = 0.f;
#pragma unroll
    for (int dd2 = 0; dd2 < DD; ++dd2) {
        const float sv = s_st[g][dd2];
        q  = fmaf(sv, Wq[dd2 * DD + d], q);
        kk = fmaf(sv, Wk[dd2 * DD + d], kk);
        vv = fmaf(sv, Wv[dd2 * DD + d], vv);
    }
    s_q[g][d] = q; s_k[g][d] = kk; s_v[g][d] = vv;
    __syncthreads();

    {
        const int kidx = d;
        float lg = 0.f;
#pragma unroll
        for (int dd2 = 0; dd2 < DD; ++dd2)
            lg = fmaf(s_q[g][dd2], s_k[kidx][dd2], lg);
        lg *= 0.17677669529663687f;
        float m = lg;
#pragma unroll
        for (int o = 16; o; o >>= 1) m = fmaxf(m, __shfl_xor_sync(0xffffffffu, m, o));
        const float e = __expf(lg - m);
        float ssum = e;
#pragma unroll
        for (int o = 16; o; o >>= 1) ssum += __shfl_xor_sync(0xffffffffu, ssum, o);
        s_attn[g][kidx] = e / ssum;
    }
    __syncthreads();

    float ot = st;
#pragma unroll
    for (int kidx = 0; kidx < GG; ++kidx)
        ot = fmaf(s_attn[g][kidx], s_v[kidx][d], ot);

    float s1 = ot, s2o = ot * ot;
#pragma unroll
    for (int o = 16; o; o >>= 1) {
        s1  += __shfl_xor_sync(0xffffffffu, s1,  o);
        s2o += __shfl_xor_sync(0xffffffffu, s2o, o);
    }
    const float mu   = s1 * (1.f / DD);
    const float var  = s2o * (1.f / DD) - mu * mu;
    const float rstd = rsqrtf(var + 1e-5f);
    const float hn = (ot - mu) * rstd * tln_g[d] + tln_b[d];
    __syncthreads();
    s_st[g][d] = hn;
    __syncthreads();

#pragma unroll
    for (int jj = 0; jj < 4; ++jj) {
        const int j = d + 32 * jj;
        float a = b1[j];
#pragma unroll
        for (int dd2 = 0; dd2 < DD; ++dd2)
            a = fmaf(s_st[g][dd2], W1[dd2 * (4 * DD) + j], a);
        a = 0.5f * a * (1.0f + erff(a * 0.70710678118654752f));
        s_h1[g][j] = a;
    }
    __syncthreads();

    float tk = b2[d];
#pragma unroll
    for (int j = 0; j < 4 * DD; ++j)
        tk = fmaf(s_h1[g][j], W2[j * DD + d], tk);
    tk += ot;
    g_tokens[(((size_t)b * HH + h) * GG + g) * DD + d] = tk;
}

// ---------------- K3: LN, combine, Wo GEMM + residual -----------------------
__global__ void __launch_bounds__(256, 2)
k3_combine(const float* __restrict__ fx,
           const float* __restrict__ ln_g, const float* __restrict__ ln_b,
           const float* __restrict__ Wo,  const float* __restrict__ bo,
           float* __restrict__ out)
{
    extern __shared__ float sm[];
    float* s_A   = sm;                   // fx -> fx_norm
    float* s_B   = sm + TOK * CC;        // slice_w; later overlaid as W panels
    float* s_C   = sm + 2 * TOK * CC;    // out_x -> Wo result (in place)

    const int tid  = threadIdx.x;
    const int tg   = tid >> 5;
    const int lane = tid & 31;
    const int batch = blockIdx.x / BLKS_PER_BATCH;
    const int n0    = (blockIdx.x % BLKS_PER_BATCH) * TOK;

    const float* fxp = fx + ((size_t)batch * NN + n0) * CC;
    for (int i = tid * 4; i < TOK * CC; i += 1024)
        *reinterpret_cast<float4*>(&s_A[i]) = *reinterpret_cast<const float4*>(&fxp[i]);
    const float* swp = g_slice_w + ((size_t)batch * NN + n0) * (HH * GG);
    for (int i = tid * 4; i < TOK * (HH * GG); i += 1024)
        *reinterpret_cast<float4*>(&s_B[i]) = *reinterpret_cast<const float4*>(&swp[i]);

    // tokens for head h=tg, component d=lane, all g: registers
    float tokr[GG];
#pragma unroll
    for (int g = 0; g < GG; ++g)
        tokr[g] = g_tokens[(((size_t)batch * HH + tg) * GG + g) * DD + lane];
    __syncthreads();

    ln_rows(s_A, ln_g, ln_b, tg, lane);

    // out_x: warp tg = head, lane = d
    for (int t = 0; t < TOK; ++t) {
        float a = 0.f;
#pragma unroll
        for (int g = 0; g < GG; ++g)
            a = fmaf(tokr[g], s_B[t * CC + tg * GG + g], a);
        s_C[t * CC + tg * DD + lane] = a;
    }
    __syncthreads();   // slice_w dead after this point -> s_B becomes panel buf

    gemm2<16>(s_C, Wo, bo, s_C, s_B);   // in-place (warp-row-exclusive)
    __syncthreads();

    float* op = out + ((size_t)batch * NN + n0) * CC;
    for (int i = tid * 4; i < TOK * CC; i += 1024) {
        float4 c4 = *reinterpret_cast<float4*>(&s_C[i]);
        const float4 a4 = *reinterpret_cast<const float4*>(&s_A[i]);
        c4.x += a4.x; c4.y += a4.y; c4.z += a4.z; c4.w += a4.w;
        *reinterpret_cast<float4*>(&op[i]) = c4;
    }
}

// ---------------- launch -----------------------------------------------------
extern "C" void kernel_launch(void* const* d_in, const int* in_sizes, int n_in,
                              void* d_out, int out_size)
{
    const float* fx    = (const float*)d_in[0];
    const float* ln_g  = (const float*)d_in[1];
    const float* ln_b  = (const float*)d_in[2];
    const float* Wx    = (const float*)d_in[3];
    const float* bx    = (const float*)d_in[4];
    const float* Wfx   = (const float*)d_in[5];
    const float* bfx   = (const float*)d_in[6];
    const float* Ws    = (const float*)d_in[7];
    const float* bs    = (const float*)d_in[8];
    const float* tempp = (const float*)d_in[9];
    const float* Wq    = (const float*)d_in[10];
    const float* Wk    = (const float*)d_in[11];
    const float* Wv    = (const float*)d_in[12];
    const float* tln_g = (const float*)d_in[13];
    const float* tln_b = (const float*)d_in[14];
    const float* W1    = (const float*)d_in[15];
    const float* b1    = (const float*)d_in[16];
    const float* W2    = (const float*)d_in[17];
    const float* b2    = (const float*)d_in[18];
    const float* Wo    = (const float*)d_in[19];
    const float* bo    = (const float*)d_in[20];
    float* out = (float*)d_out;

    const int smem1 = (2 * TOK * CC + 8192 + DD * GG + GG) * (int)sizeof(float); // ~100KB
    const int smem3 = (3 * TOK * CC) * (int)sizeof(float);                       // 96KB
    static int s_init = 0;
    if (!s_init) {
        cudaFuncSetAttribute(k1_dispatch, cudaFuncAttributeMaxDynamicSharedMemorySize, smem1);
        cudaFuncSetAttribute(k3_combine,  cudaFuncAttributeMaxDynamicSharedMemorySize, smem3);
        s_init = 1;
    }

    k1_dispatch<<<NBLK, 256, smem1>>>(fx, ln_g, ln_b, Wx, bx, Wfx, bfx, Ws, bs, tempp);
    k2_tokens<<<BB * HH, 1024>>>(Wq, Wk, Wv, tln_g, tln_b, W1, b1, W2, b2);
    k3_combine<<<NBLK, 256, smem3>>>(fx, ln_g, ln_b, Wo, bo, out);
}